// round 14
// baseline (speedup 1.0000x reference)
#include <cuda_runtime.h>
#include <cuda_fp16.h>
#include <cstdint>
#include <math.h>

// ---------------- problem dims ----------------
#define BB    1024
#define DIN   2048
#define DINT  8192
#define NGIN  16
#define NGINT 64

// ---------------- scratch (device globals) ----------------
__device__ __half g_x_h  [BB * DIN];
__device__ __half g_rotg_h[NGIN  * 128 * 128];
__device__ __half g_rotu_h[NGIN  * 128 * 128];
__device__ __half g_rotd_h[NGINT * 128 * 128];
__device__ __half g_Wg   [DINT * DIN];
__device__ __half g_Wu   [DINT * DIN];
__device__ __half g_Wd   [DIN * DINT];
__device__ __half g_xrg  [BB * DIN];
__device__ __half g_xru  [BB * DIN];
__device__ __half g_gate [BB * DINT];
__device__ __half g_h    [BB * DINT];
__device__ __half g_hr   [BB * DINT];
__device__ float  g_part [2 * BB * DIN];

// ---------------- converts (one launch) ----------------
#define CVT_N0 (BB * DIN / 4)
#define CVT_N1 (NGIN * 128 * 128 / 4)
#define CVT_N2 (NGIN * 128 * 128 / 4)
#define CVT_N3 (NGINT * 128 * 128 / 4)
#define CVT_TOT (CVT_N0 + CVT_N1 + CVT_N2 + CVT_N3)

__global__ void k_convert_all(const float4* __restrict__ x, const float4* __restrict__ rg,
                              const float4* __restrict__ ru, const float4* __restrict__ rd,
                              __half2* __restrict__ ox, __half2* __restrict__ org,
                              __half2* __restrict__ oru, __half2* __restrict__ ord) {
    int i = blockIdx.x * blockDim.x + threadIdx.x;
    if (i >= CVT_TOT) return;
    const float4* in;
    __half2* out;
    int j = i;
    if (j < CVT_N0)                       { in = x;  out = ox;  }
    else if ((j -= CVT_N0) < CVT_N1)      { in = rg; out = org; }
    else if ((j -= CVT_N1) < CVT_N2)      { in = ru; out = oru; }
    else { j -= CVT_N2;                     in = rd; out = ord; }
    float4 v = in[j];
    out[2 * j]     = __floats2half2_rn(v.x, v.y);
    out[2 * j + 1] = __floats2half2_rn(v.z, v.w);
}

__device__ __forceinline__ uint32_t pack2(int v, const float* lut, float s) {
    __half2 h = __floats2half2_rn(lut[v & 15] * s, lut[(v >> 4) & 15] * s);
    return *reinterpret_cast<uint32_t*>(&h);
}

__global__ void k_reduce2(const float4* __restrict__ p0, const float4* __restrict__ p1,
                          const float* __restrict__ bias, float4* __restrict__ out,
                          int n4, int ldc4) {
    int i = blockIdx.x * blockDim.x + threadIdx.x;
    if (i >= n4) return;
    float4 a = p0[i], b = p1[i];
    int c4 = i % ldc4;
    const float4 bv = reinterpret_cast<const float4*>(bias)[c4];
    float4 o;
    o.x = a.x + b.x + bv.x;
    o.y = a.y + b.y + bv.y;
    o.z = a.z + b.z + bv.z;
    o.w = a.w + b.w + bv.w;
    out[i] = o;
}

// ---------------- GEMM machinery ----------------
#define STAGES 4     // phase1 rot-GEMM (BK=32 legacy path)
#define SLDK   40
// main GEMM: BK=64, 3 stages, XOR-swizzled 128B rows
#define STG2   3
#define STAGE_H (128 * 64)
#define SMEM_G2 (STG2 * STAGE_H * 2 * 2)   // 98304 B

__device__ __forceinline__ void cpasync16(void* s, const void* g) {
    uint32_t sa = (uint32_t)__cvta_generic_to_shared(s);
    asm volatile("cp.async.cg.shared.global [%0], [%1], 16;\n" :: "r"(sa), "l"(g));
}
__device__ __forceinline__ void ldm4(uint32_t& r0, uint32_t& r1, uint32_t& r2, uint32_t& r3,
                                     const void* p) {
    uint32_t a = (uint32_t)__cvta_generic_to_shared(p);
    asm volatile("ldmatrix.sync.aligned.m8n8.x4.shared.b16 {%0,%1,%2,%3}, [%4];"
                 : "=r"(r0), "=r"(r1), "=r"(r2), "=r"(r3) : "r"(a));
}
__device__ __forceinline__ void mma16816(float* c, const uint32_t* a, const uint32_t* b) {
    asm volatile(
        "mma.sync.aligned.m16n8k16.row.col.f32.f16.f16.f32 "
        "{%0,%1,%2,%3}, {%4,%5,%6,%7}, {%8,%9}, {%0,%1,%2,%3};"
        : "+f"(c[0]), "+f"(c[1]), "+f"(c[2]), "+f"(c[3])
        : "r"(a[0]), "r"(a[1]), "r"(a[2]), "r"(a[3]), "r"(b[0]), "r"(b[1]));
}

// ---------------- fused gate+up+SwiGLU kernel ----------------
// grid (8, 64): each CTA computes gate tile (m0,n0) then up tile (m0,n0);
// up epilogue reads back the gate values this same thread wrote (same-thread RAW).
__global__ void __launch_bounds__(256, 2)
k_gateup(const __half* __restrict__ xrg, const __half* __restrict__ xru,
         const __half* __restrict__ Wg, const __half* __restrict__ Wu,
         const float* __restrict__ gbias, const float* __restrict__ ubias,
         __half* __restrict__ gateh, __half* __restrict__ hh) {
    extern __shared__ __half sm[];
    __half* As = sm;
    __half* Bs = sm + STG2 * STAGE_H;

    const int tid = threadIdx.x, lane = tid & 31, wid = tid >> 5;
    const int wm = wid >> 2, wn = wid & 3;
    const int m0 = blockIdx.x * 128, n0 = blockIdx.y * 128;
    const int kt = DIN >> 6;           // 32
    const int rw = tid >> 3, kc = tid & 7;
    const int crow = wm * 64 + (lane >> 2);
    const int ccol = wn * 32 + (lane & 3) * 2;

#pragma unroll 1
    for (int phase = 0; phase < 2; phase++) {
        const __half* A  = phase ? xru : xrg;
        const __half* Bw = phase ? Wu  : Wg;
        const float* bias = phase ? ubias : gbias;

        float acc[4][4][4];
#pragma unroll
        for (int i = 0; i < 4; i++)
#pragma unroll
            for (int j = 0; j < 4; j++)
#pragma unroll
                for (int k = 0; k < 4; k++) acc[i][j][k] = 0.f;

        auto issue = [&](int t) {
            int slot = t % STG2;
            __half* as = As + slot * STAGE_H;
            __half* bs = Bs + slot * STAGE_H;
            int k0 = t << 6;
#pragma unroll
            for (int j = 0; j < 4; j++) {
                int row = rw + 32 * j;
                uint32_t so = (uint32_t)row * 64 + (uint32_t)((kc ^ (row & 7)) * 8);
                cpasync16(as + so, A  + (size_t)(m0 + row) * DIN + k0 + kc * 8);
                cpasync16(bs + so, Bw + (size_t)(n0 + row) * DIN + k0 + kc * 8);
            }
        };

        issue(0);
        asm volatile("cp.async.commit_group;");
        issue(1);
        asm volatile("cp.async.commit_group;");

        for (int t = 0; t < kt; t++) {
            asm volatile("cp.async.wait_group %0;" :: "n"(1));
            __syncthreads();
            int nt = t + 2;
            if (nt < kt) issue(nt);
            asm volatile("cp.async.commit_group;");

            int slot = t % STG2;
            const __half* as = As + slot * STAGE_H;
            const __half* bs = Bs + slot * STAGE_H;
#pragma unroll
            for (int kk = 0; kk < 4; kk++) {
                uint32_t af[4][4], bf[4][2];
#pragma unroll
                for (int mi = 0; mi < 4; mi++) {
                    int ar = wm * 64 + mi * 16 + (lane & 15);
                    int ch = kk * 2 + (lane >> 4);
                    const __half* p = as + ar * 64 + ((ch ^ (ar & 7)) * 8);
                    ldm4(af[mi][0], af[mi][1], af[mi][2], af[mi][3], p);
                }
#pragma unroll
                for (int nb = 0; nb < 2; nb++) {
                    int br = wn * 32 + nb * 16 + (lane & 7) + ((lane >> 4) << 3);
                    int ch = kk * 2 + ((lane >> 3) & 1);
                    const __half* p = bs + br * 64 + ((ch ^ (br & 7)) * 8);
                    uint32_t q0, q1, q2, q3;
                    ldm4(q0, q1, q2, q3, p);
                    bf[nb * 2][0] = q0; bf[nb * 2][1] = q1;
                    bf[nb * 2 + 1][0] = q2; bf[nb * 2 + 1][1] = q3;
                }
#pragma unroll
                for (int mi = 0; mi < 4; mi++)
#pragma unroll
                    for (int ni = 0; ni < 4; ni++)
                        mma16816(acc[mi][ni], af[mi], bf[ni]);
            }
        }
        // all smem reads done before next phase's issues overwrite stages
        __syncthreads();

        // epilogue
#pragma unroll
        for (int mi = 0; mi < 4; mi++) {
#pragma unroll
            for (int ni = 0; ni < 4; ni++) {
                int gr = m0 + crow + mi * 16;
                int gc = n0 + ccol + ni * 8;
                float b0 = bias[gc], b1 = bias[gc + 1];
                float v0 = acc[mi][ni][0] + b0, v1 = acc[mi][ni][1] + b1;
                float v2 = acc[mi][ni][2] + b0, v3 = acc[mi][ni][3] + b1;
                if (phase == 0) {
                    *reinterpret_cast<__half2*>(&gateh[(size_t)gr * DINT + gc]) =
                        __floats2half2_rn(v0, v1);
                    *reinterpret_cast<__half2*>(&gateh[(size_t)(gr + 8) * DINT + gc]) =
                        __floats2half2_rn(v2, v3);
                } else {
                    __half2 ga = *reinterpret_cast<const __half2*>(&gateh[(size_t)gr * DINT + gc]);
                    __half2 gb = *reinterpret_cast<const __half2*>(&gateh[(size_t)(gr + 8) * DINT + gc]);
                    float g0 = __half2float(ga.x), g1 = __half2float(ga.y);
                    float g2 = __half2float(gb.x), g3 = __half2float(gb.y);
                    v0 *= g0 / (1.f + __expf(-g0));
                    v1 *= g1 / (1.f + __expf(-g1));
                    v2 *= g2 / (1.f + __expf(-g2));
                    v3 *= g3 / (1.f + __expf(-g3));
                    *reinterpret_cast<__half2*>(&hh[(size_t)gr * DINT + gc]) =
                        __floats2half2_rn(v0, v1);
                    *reinterpret_cast<__half2*>(&hh[(size_t)(gr + 8) * DINT + gc]) =
                        __floats2half2_rn(v2, v3);
                }
            }
        }
    }
}

// EPI: 1 = half out (rot GEMMs). 4 = raw float out (split-K partial).
template<int EPI>
__global__ void __launch_bounds__(256, 2)
k_gemm(const __half* __restrict__ A, const __half* __restrict__ B,
       const float* __restrict__ bias, const __half* __restrict__ aux,
       void* __restrict__ C,
       int M, int N, int K, int lda, int ldb, int ldc,
       int aColOff, int bBatch, int cColOff, int cBatch) {
    extern __shared__ __half sm[];
    __half* As = sm;
    __half* Bs = sm + STG2 * STAGE_H;

    const int tid = threadIdx.x, lane = tid & 31, wid = tid >> 5;
    const int wm = wid >> 2, wn = wid & 3;
    const int m0 = blockIdx.x * 128, n0 = blockIdx.y * 128;
    const __half* Ab = A + (size_t)blockIdx.z * aColOff;
    const __half* Bb = B + (size_t)blockIdx.z * bBatch;
    const int kt = K >> 6;

    float acc[4][4][4];
#pragma unroll
    for (int i = 0; i < 4; i++)
#pragma unroll
        for (int j = 0; j < 4; j++)
#pragma unroll
            for (int k = 0; k < 4; k++) acc[i][j][k] = 0.f;

    const int rw = tid >> 3;
    const int kc = tid & 7;

    auto issue = [&](int t) {
        int slot = t % STG2;
        __half* as = As + slot * STAGE_H;
        __half* bs = Bs + slot * STAGE_H;
        int k0 = t << 6;
#pragma unroll
        for (int j = 0; j < 4; j++) {
            int row = rw + 32 * j;
            uint32_t so = (uint32_t)row * 64 + (uint32_t)((kc ^ (row & 7)) * 8);
            cpasync16(as + so, Ab + (size_t)(m0 + row) * lda + k0 + kc * 8);
            cpasync16(bs + so, Bb + (size_t)(n0 + row) * ldb + k0 + kc * 8);
        }
    };

    issue(0);
    asm volatile("cp.async.commit_group;");
    if (1 < kt) issue(1);
    asm volatile("cp.async.commit_group;");

    for (int t = 0; t < kt; t++) {
        asm volatile("cp.async.wait_group %0;" :: "n"(1));
        __syncthreads();
        int nt = t + 2;
        if (nt < kt) issue(nt);
        asm volatile("cp.async.commit_group;");

        int slot = t % STG2;
        const __half* as = As + slot * STAGE_H;
        const __half* bs = Bs + slot * STAGE_H;
#pragma unroll
        for (int kk = 0; kk < 4; kk++) {
            uint32_t af[4][4], bf[4][2];
#pragma unroll
            for (int mi = 0; mi < 4; mi++) {
                int ar = wm * 64 + mi * 16 + (lane & 15);
                int ch = kk * 2 + (lane >> 4);
                const __half* p = as + ar * 64 + ((ch ^ (ar & 7)) * 8);
                ldm4(af[mi][0], af[mi][1], af[mi][2], af[mi][3], p);
            }
#pragma unroll
            for (int nb = 0; nb < 2; nb++) {
                int br = wn * 32 + nb * 16 + (lane & 7) + ((lane >> 4) << 3);
                int ch = kk * 2 + ((lane >> 3) & 1);
                const __half* p = bs + br * 64 + ((ch ^ (br & 7)) * 8);
                uint32_t q0, q1, q2, q3;
                ldm4(q0, q1, q2, q3, p);
                bf[nb * 2][0] = q0; bf[nb * 2][1] = q1;
                bf[nb * 2 + 1][0] = q2; bf[nb * 2 + 1][1] = q3;
            }
#pragma unroll
            for (int mi = 0; mi < 4; mi++)
#pragma unroll
                for (int ni = 0; ni < 4; ni++)
                    mma16816(acc[mi][ni], af[mi], bf[ni]);
        }
    }

    // epilogue
    const int crow = wm * 64 + (lane >> 2);
    const int ccol = wn * 32 + (lane & 3) * 2;
#pragma unroll
    for (int mi = 0; mi < 4; mi++) {
#pragma unroll
        for (int ni = 0; ni < 4; ni++) {
            int gr = m0 + crow + mi * 16;
            int gc = n0 + ccol + ni * 8 + blockIdx.z * cColOff;
            float v0 = acc[mi][ni][0], v1 = acc[mi][ni][1];
            float v2 = acc[mi][ni][2], v3 = acc[mi][ni][3];
            if (EPI == 4) {
                float* Cf = (float*)C + (size_t)blockIdx.z * cBatch;
                *reinterpret_cast<float2*>(&Cf[(size_t)gr * ldc + gc])       = make_float2(v0, v1);
                *reinterpret_cast<float2*>(&Cf[(size_t)(gr + 8) * ldc + gc]) = make_float2(v2, v3);
            } else {
                __half* Ch = (__half*)C;
                *reinterpret_cast<__half2*>(&Ch[(size_t)gr * ldc + gc])       = __floats2half2_rn(v0, v1);
                *reinterpret_cast<__half2*>(&Ch[(size_t)(gr + 8) * ldc + gc]) = __floats2half2_rn(v2, v3);
            }
        }
    }
}

// ---------------- phase 1 (unchanged) ----------------
#define DQ_BPM   2048
#define DQ_INT4  ((long)DQ_BPM * 256)

__global__ void __launch_bounds__(256, 2)
k_phase1(const __half* __restrict__ xh,
         const __half* __restrict__ rgh, const __half* __restrict__ ruh,
         __half* __restrict__ xrg, __half* __restrict__ xru,
         const int* __restrict__ gp, const int* __restrict__ upk, const int* __restrict__ dpk,
         const float* __restrict__ cb,
         const float* __restrict__ gn, const float* __restrict__ un, const float* __restrict__ dn,
         __half* __restrict__ wg, __half* __restrict__ wu, __half* __restrict__ wd) {
    extern __shared__ __half sm[];
    const int tid = threadIdx.x;

    if (blockIdx.x >= 256) {
        float* lut = (float*)sm;
        if (tid < 16) lut[tid] = cb[tid] * 0.08838834764831845f;
        __syncthreads();
        int j = blockIdx.x - 256;
        int z = j / DQ_BPM, bb = j % DQ_BPM;
        const int* packed  = (z == 0) ? gp : (z == 1) ? upk : dpk;
        const float* norms = (z == 0) ? gn : (z == 1) ? un  : dn;
        __half* out        = (z == 0) ? wg : (z == 1) ? wu  : wd;
        const int K  = (z == 2) ? DINT : DIN;
        const int Kh = K >> 1;
        const int ng = K >> 7;
        long base = (long)bb * 256 + tid;
        int4 pk[4];
        float s[4];
        long idx[4];
#pragma unroll
        for (int p = 0; p < 4; p++) {
            idx[p] = base + p * DQ_INT4;
            pk[p] = reinterpret_cast<const int4*>(packed)[idx[p]];
            long p0 = idx[p] * 4;
            int n  = (int)(p0 / Kh);
            int k0 = (int)(p0 % Kh) * 2;
            s[p] = norms[(long)n * ng + (k0 >> 7)];
        }
#pragma unroll
        for (int p = 0; p < 4; p++) {
            uint4 o;
            o.x = pack2(pk[p].x, lut, s[p]);
            o.y = pack2(pk[p].y, lut, s[p]);
            o.z = pack2(pk[p].z, lut, s[p]);
            o.w = pack2(pk[p].w, lut, s[p]);
            reinterpret_cast<uint4*>(out)[idx[p]] = o;
        }
        return;
    }

    // rotation GEMM branch (K=128, BK=32, 4 ktiles)
    __half* As = sm;
    __half* Bs = sm + STAGES * 128 * SLDK;

    const int path = blockIdx.x >> 7;
    const int r    = blockIdx.x & 127;
    const int m0   = (r & 7) * 128;
    const int grp  = r >> 3;
    const __half* Ab = xh + grp * 128;
    const __half* Bb = (path ? ruh : rgh) + (size_t)grp * 128 * 128;
    __half* Ch = path ? xru : xrg;
    const int colBase = grp * 128;

    const int lane = tid & 31, wid = tid >> 5;
    const int wm = wid >> 2, wn = wid & 3;

    float acc[4][4][4];
#pragma unroll
    for (int i = 0; i < 4; i++)
#pragma unroll
        for (int jj = 0; jj < 4; jj++)
#pragma unroll
            for (int k = 0; k < 4; k++) acc[i][jj][k] = 0.f;

    const int c1 = tid, c2 = tid + 256;
    const int r1 = c1 >> 2, kc1 = c1 & 3, r2 = c2 >> 2, kc2 = c2 & 3;

    auto issue = [&](int t) {
        int slot = t & (STAGES - 1);
        __half* as = As + slot * 128 * SLDK;
        __half* bs = Bs + slot * 128 * SLDK;
        int k0 = t << 5;
        cpasync16(as + r1 * SLDK + kc1 * 8, Ab + (size_t)(m0 + r1) * DIN + k0 + kc1 * 8);
        cpasync16(as + r2 * SLDK + kc2 * 8, Ab + (size_t)(m0 + r2) * DIN + k0 + kc2 * 8);
        cpasync16(bs + r1 * SLDK + kc1 * 8, Bb + (size_t)r1 * 128 + k0 + kc1 * 8);
        cpasync16(bs + r2 * SLDK + kc2 * 8, Bb + (size_t)r2 * 128 + k0 + kc2 * 8);
    };

#pragma unroll
    for (int t = 0; t < STAGES - 1; t++) {
        issue(t);
        asm volatile("cp.async.commit_group;");
    }

#pragma unroll
    for (int t = 0; t < 4; t++) {
        asm volatile("cp.async.wait_group %0;" :: "n"(STAGES - 2));
        __syncthreads();
        if (t == 0) issue(3);
        asm volatile("cp.async.commit_group;");

        int slot = t & (STAGES - 1);
        const __half* as = As + slot * 128 * SLDK;
        const __half* bs = Bs + slot * 128 * SLDK;
#pragma unroll
        for (int kk = 0; kk < 2; kk++) {
            uint32_t af[4][4], bf[4][2];
#pragma unroll
            for (int mi = 0; mi < 4; mi++) {
                const __half* p = as + (wm * 64 + mi * 16 + (lane & 15)) * SLDK
                                     + kk * 16 + (lane >> 4) * 8;
                ldm4(af[mi][0], af[mi][1], af[mi][2], af[mi][3], p);
            }
#pragma unroll
            for (int nb = 0; nb < 2; nb++) {
                const __half* p = bs + (wn * 32 + nb * 16 + (lane & 7) + ((lane >> 4) << 3)) * SLDK
                                     + kk * 16 + (((lane >> 3) & 1) << 3);
                uint32_t q0, q1, q2, q3;
                ldm4(q0, q1, q2, q3, p);
                bf[nb * 2][0] = q0; bf[nb * 2][1] = q1;
                bf[nb * 2 + 1][0] = q2; bf[nb * 2 + 1][1] = q3;
            }
#pragma unroll
            for (int mi = 0; mi < 4; mi++)
#pragma unroll
                for (int ni = 0; ni < 4; ni++)
                    mma16816(acc[mi][ni], af[mi], bf[ni]);
        }
    }

    const int crow = wm * 64 + (lane >> 2);
    const int ccol = wn * 32 + (lane & 3) * 2;
#pragma unroll
    for (int mi = 0; mi < 4; mi++) {
#pragma unroll
        for (int ni = 0; ni < 4; ni++) {
            int gr = m0 + crow + mi * 16;
            int gc = colBase + ccol + ni * 8;
            *reinterpret_cast<__half2*>(&Ch[(size_t)gr * DIN + gc]) =
                __floats2half2_rn(acc[mi][ni][0], acc[mi][ni][1]);
            *reinterpret_cast<__half2*>(&Ch[(size_t)(gr + 8) * DIN + gc]) =
                __floats2half2_rn(acc[mi][ni][2], acc[mi][ni][3]);
        }
    }
}

// ---------------- host ----------------
template<typename T>
static void* symaddr(T& sym_) {
    void* p = nullptr;
    cudaGetSymbolAddress(&p, sym_);
    return p;
}

extern "C" void kernel_launch(void* const* d_in, const int* in_sizes, int n_in,
                              void* d_out, int out_size) {
    (void)in_sizes; (void)n_in; (void)out_size;
    const float* x     = (const float*)d_in[0];
    const float* cb    = (const float*)d_in[1];
    const float* gnorm = (const float*)d_in[2];
    const float* gbias = (const float*)d_in[3];
    const float* unorm = (const float*)d_in[4];
    const float* ubias = (const float*)d_in[5];
    const float* dnorm = (const float*)d_in[6];
    const float* dbias = (const float*)d_in[7];
    const float* rotg  = (const float*)d_in[8];
    const float* rotu  = (const float*)d_in[9];
    const float* rotd  = (const float*)d_in[10];
    const int*   gp    = (const int*)d_in[11];
    const int*   up_   = (const int*)d_in[12];
    const int*   dp    = (const int*)d_in[13];
    float* out = (float*)d_out;

    __half* xh    = (__half*)symaddr(g_x_h);
    __half* rgh   = (__half*)symaddr(g_rotg_h);
    __half* ruh   = (__half*)symaddr(g_rotu_h);
    __half* rdh   = (__half*)symaddr(g_rotd_h);
    __half* Wg    = (__half*)symaddr(g_Wg);
    __half* Wu    = (__half*)symaddr(g_Wu);
    __half* Wd    = (__half*)symaddr(g_Wd);
    __half* xrg   = (__half*)symaddr(g_xrg);
    __half* xru   = (__half*)symaddr(g_xru);
    __half* gateh = (__half*)symaddr(g_gate);
    __half* hh    = (__half*)symaddr(g_h);
    __half* hr    = (__half*)symaddr(g_hr);
    float*  part  = (float*)symaddr(g_part);

    const int TPB = 256;
    const int smemP1 = STAGES * 2 * 128 * SLDK * (int)sizeof(__half); // 81920
    cudaFuncSetAttribute(k_gemm<1>, cudaFuncAttributeMaxDynamicSharedMemorySize, SMEM_G2);
    cudaFuncSetAttribute(k_gemm<4>, cudaFuncAttributeMaxDynamicSharedMemorySize, SMEM_G2);
    cudaFuncSetAttribute(k_gateup,  cudaFuncAttributeMaxDynamicSharedMemorySize, SMEM_G2);
    cudaFuncSetAttribute(k_phase1,  cudaFuncAttributeMaxDynamicSharedMemorySize, smemP1);

    // all fp32 -> fp16 converts in one launch
    k_convert_all<<<(CVT_TOT + TPB - 1) / TPB, TPB>>>(
        (const float4*)x, (const float4*)rotg, (const float4*)rotu, (const float4*)rotd,
        (__half2*)xh, (__half2*)rgh, (__half2*)ruh, (__half2*)rdh);

    // phase 1: both x-rotations + all three dequants
    k_phase1<<<256 + 3 * DQ_BPM, TPB, smemP1>>>(
        xh, rgh, ruh, xrg, xru, gp, up_, dp, cb, gnorm, unorm, dnorm, Wg, Wu, Wd);

    // fused gate + up + SwiGLU: each CTA does gate tile then up tile (same coords)
    k_gateup<<<dim3(BB / 128, DINT / 128), 256, SMEM_G2>>>(
        xrg, xru, Wg, Wu, gbias, ubias, gateh, hh);

    // per-group rotation of h (K=128 -> kt=2)
    k_gemm<1><<<dim3(BB / 128, 1, NGINT), 256, SMEM_G2>>>(
        hh, rdh, nullptr, nullptr, hr, BB, 128, 128, DINT, 128, DINT, 128, 128 * 128, 128, 0);

    // down GEMM split-K=2
    k_gemm<4><<<dim3(BB / 128, DIN / 128, 2), 256, SMEM_G2>>>(
        hr, Wd, nullptr, nullptr, part, BB, DIN, DINT / 2, DINT, DINT, DIN,
        DINT / 2, DINT / 2, 0, BB * DIN);

    // out = part0 + part1 + dbias
    {
        int n4r = BB * DIN / 4;
        k_reduce2<<<(n4r + TPB - 1) / TPB, TPB>>>(
            (const float4*)part, (const float4*)(part + BB * DIN), dbias,
            (float4*)out, n4r, DIN / 4);
    }
}

// round 15
// speedup vs baseline: 1.0219x; 1.0219x over previous
#include <cuda_runtime.h>
#include <cuda_fp16.h>
#include <cstdint>
#include <math.h>

// ---------------- problem dims ----------------
#define BB    1024
#define DIN   2048
#define DINT  8192
#define NGIN  16
#define NGINT 64

// ---------------- scratch (device globals) ----------------
__device__ __half g_x_h  [BB * DIN];
__device__ __half g_rotg_h[NGIN  * 128 * 128];
__device__ __half g_rotu_h[NGIN  * 128 * 128];
__device__ __half g_rotd_h[NGINT * 128 * 128];
__device__ __half g_Wg   [DINT * DIN];
__device__ __half g_Wu   [DINT * DIN];
__device__ __half g_Wd   [DIN * DINT];
__device__ __half g_xrg  [BB * DIN];
__device__ __half g_xru  [BB * DIN];
__device__ __half g_gate [BB * DINT];
__device__ __half g_hr   [BB * DINT];
__device__ float  g_part [2 * BB * DIN];

// ---------------- converts (one launch) ----------------
#define CVT_N0 (BB * DIN / 4)
#define CVT_N1 (NGIN * 128 * 128 / 4)
#define CVT_N2 (NGIN * 128 * 128 / 4)
#define CVT_N3 (NGINT * 128 * 128 / 4)
#define CVT_TOT (CVT_N0 + CVT_N1 + CVT_N2 + CVT_N3)

__global__ void k_convert_all(const float4* __restrict__ x, const float4* __restrict__ rg,
                              const float4* __restrict__ ru, const float4* __restrict__ rd,
                              __half2* __restrict__ ox, __half2* __restrict__ org,
                              __half2* __restrict__ oru, __half2* __restrict__ ord) {
    int i = blockIdx.x * blockDim.x + threadIdx.x;
    if (i >= CVT_TOT) return;
    const float4* in;
    __half2* out;
    int j = i;
    if (j < CVT_N0)                       { in = x;  out = ox;  }
    else if ((j -= CVT_N0) < CVT_N1)      { in = rg; out = org; }
    else if ((j -= CVT_N1) < CVT_N2)      { in = ru; out = oru; }
    else { j -= CVT_N2;                     in = rd; out = ord; }
    float4 v = in[j];
    out[2 * j]     = __floats2half2_rn(v.x, v.y);
    out[2 * j + 1] = __floats2half2_rn(v.z, v.w);
}

__device__ __forceinline__ uint32_t pack2(int v, const float* lut, float s) {
    __half2 h = __floats2half2_rn(lut[v & 15] * s, lut[(v >> 4) & 15] * s);
    return *reinterpret_cast<uint32_t*>(&h);
}

__global__ void k_reduce2(const float4* __restrict__ p0, const float4* __restrict__ p1,
                          const float* __restrict__ bias, float4* __restrict__ out,
                          int n4, int ldc4) {
    int i = blockIdx.x * blockDim.x + threadIdx.x;
    if (i >= n4) return;
    float4 a = p0[i], b = p1[i];
    int c4 = i % ldc4;
    const float4 bv = reinterpret_cast<const float4*>(bias)[c4];
    float4 o;
    o.x = a.x + b.x + bv.x;
    o.y = a.y + b.y + bv.y;
    o.z = a.z + b.z + bv.z;
    o.w = a.w + b.w + bv.w;
    out[i] = o;
}

// ---------------- GEMM machinery ----------------
#define STAGES 4     // phase1 rot-GEMM (BK=32 legacy path)
#define SLDK   40
#define STG2   3
#define STAGE_H (128 * 64)
#define SMEM_G2 (STG2 * STAGE_H * 2 * 2)   // 98304 B

__device__ __forceinline__ void cpasync16(void* s, const void* g) {
    uint32_t sa = (uint32_t)__cvta_generic_to_shared(s);
    asm volatile("cp.async.cg.shared.global [%0], [%1], 16;\n" :: "r"(sa), "l"(g));
}
__device__ __forceinline__ void ldm4(uint32_t& r0, uint32_t& r1, uint32_t& r2, uint32_t& r3,
                                     const void* p) {
    uint32_t a = (uint32_t)__cvta_generic_to_shared(p);
    asm volatile("ldmatrix.sync.aligned.m8n8.x4.shared.b16 {%0,%1,%2,%3}, [%4];"
                 : "=r"(r0), "=r"(r1), "=r"(r2), "=r"(r3) : "r"(a));
}
__device__ __forceinline__ void mma16816(float* c, const uint32_t* a, const uint32_t* b) {
    asm volatile(
        "mma.sync.aligned.m16n8k16.row.col.f32.f16.f16.f32 "
        "{%0,%1,%2,%3}, {%4,%5,%6,%7}, {%8,%9}, {%0,%1,%2,%3};"
        : "+f"(c[0]), "+f"(c[1]), "+f"(c[2]), "+f"(c[3])
        : "r"(a[0]), "r"(a[1]), "r"(a[2]), "r"(a[3]), "r"(b[0]), "r"(b[1]));
}

// EPI: 2 = half out +bias (gate). 4 = raw float out (split-K partial).
template<int EPI>
__global__ void __launch_bounds__(256, 2)
k_gemm(const __half* __restrict__ A, const __half* __restrict__ B,
       const float* __restrict__ bias, const __half* __restrict__ aux,
       void* __restrict__ C,
       int M, int N, int K, int lda, int ldb, int ldc,
       int aColOff, int bBatch, int cColOff, int cBatch) {
    extern __shared__ __half sm[];
    __half* As = sm;
    __half* Bs = sm + STG2 * STAGE_H;

    const int tid = threadIdx.x, lane = tid & 31, wid = tid >> 5;
    const int wm = wid >> 2, wn = wid & 3;
    const int m0 = blockIdx.x * 128, n0 = blockIdx.y * 128;
    const __half* Ab = A + (size_t)blockIdx.z * aColOff;
    const __half* Bb = B + (size_t)blockIdx.z * bBatch;
    const int kt = K >> 6;

    float acc[4][4][4];
#pragma unroll
    for (int i = 0; i < 4; i++)
#pragma unroll
        for (int j = 0; j < 4; j++)
#pragma unroll
            for (int k = 0; k < 4; k++) acc[i][j][k] = 0.f;

    const int rw = tid >> 3;
    const int kc = tid & 7;

    auto issue = [&](int t) {
        int slot = t % STG2;
        __half* as = As + slot * STAGE_H;
        __half* bs = Bs + slot * STAGE_H;
        int k0 = t << 6;
#pragma unroll
        for (int j = 0; j < 4; j++) {
            int row = rw + 32 * j;
            uint32_t so = (uint32_t)row * 64 + (uint32_t)((kc ^ (row & 7)) * 8);
            cpasync16(as + so, Ab + (size_t)(m0 + row) * lda + k0 + kc * 8);
            cpasync16(bs + so, Bb + (size_t)(n0 + row) * ldb + k0 + kc * 8);
        }
    };

    issue(0);
    asm volatile("cp.async.commit_group;");
    if (1 < kt) issue(1);
    asm volatile("cp.async.commit_group;");

    for (int t = 0; t < kt; t++) {
        asm volatile("cp.async.wait_group %0;" :: "n"(1));
        __syncthreads();
        int nt = t + 2;
        if (nt < kt) issue(nt);
        asm volatile("cp.async.commit_group;");

        int slot = t % STG2;
        const __half* as = As + slot * STAGE_H;
        const __half* bs = Bs + slot * STAGE_H;
#pragma unroll
        for (int kk = 0; kk < 4; kk++) {
            uint32_t af[4][4], bf[4][2];
#pragma unroll
            for (int mi = 0; mi < 4; mi++) {
                int ar = wm * 64 + mi * 16 + (lane & 15);
                int ch = kk * 2 + (lane >> 4);
                const __half* p = as + ar * 64 + ((ch ^ (ar & 7)) * 8);
                ldm4(af[mi][0], af[mi][1], af[mi][2], af[mi][3], p);
            }
#pragma unroll
            for (int nb = 0; nb < 2; nb++) {
                int br = wn * 32 + nb * 16 + (lane & 7) + ((lane >> 4) << 3);
                int ch = kk * 2 + ((lane >> 3) & 1);
                const __half* p = bs + br * 64 + ((ch ^ (br & 7)) * 8);
                uint32_t q0, q1, q2, q3;
                ldm4(q0, q1, q2, q3, p);
                bf[nb * 2][0] = q0; bf[nb * 2][1] = q1;
                bf[nb * 2 + 1][0] = q2; bf[nb * 2 + 1][1] = q3;
            }
#pragma unroll
            for (int mi = 0; mi < 4; mi++)
#pragma unroll
                for (int ni = 0; ni < 4; ni++)
                    mma16816(acc[mi][ni], af[mi], bf[ni]);
        }
    }

    const int crow = wm * 64 + (lane >> 2);
    const int ccol = wn * 32 + (lane & 3) * 2;
#pragma unroll
    for (int mi = 0; mi < 4; mi++) {
#pragma unroll
        for (int ni = 0; ni < 4; ni++) {
            int gr = m0 + crow + mi * 16;
            int gc = n0 + ccol + ni * 8 + blockIdx.z * cColOff;
            float v0 = acc[mi][ni][0], v1 = acc[mi][ni][1];
            float v2 = acc[mi][ni][2], v3 = acc[mi][ni][3];
            if (EPI == 2) {
                float b0 = bias[gc], b1 = bias[gc + 1];
                v0 += b0; v1 += b1; v2 += b0; v3 += b1;
            }
            if (EPI == 4) {
                float* Cf = (float*)C + (size_t)blockIdx.z * cBatch;
                *reinterpret_cast<float2*>(&Cf[(size_t)gr * ldc + gc])       = make_float2(v0, v1);
                *reinterpret_cast<float2*>(&Cf[(size_t)(gr + 8) * ldc + gc]) = make_float2(v2, v3);
            } else {
                __half* Ch = (__half*)C;
                *reinterpret_cast<__half2*>(&Ch[(size_t)gr * ldc + gc])       = __floats2half2_rn(v0, v1);
                *reinterpret_cast<__half2*>(&Ch[(size_t)(gr + 8) * ldc + gc]) = __floats2half2_rn(v2, v3);
            }
        }
    }
}

// ---------------- fused up + SwiGLU + h-rotation ----------------
// grid (8, 64): tile (m0, n0) with n0 = 128*g spanning exactly rotation group g.
// Mainloop: u = xru @ Wu^T. Epilogue: h = silu(gate)*(u+bias) -> fp16 -> smem tile,
// then hr_tile = h_tile @ Rd[g]^T (K=128, 2 slabs) -> gmem. No hh round-trip.
__global__ void __launch_bounds__(256, 2)
k_uprot(const __half* __restrict__ xru, const __half* __restrict__ Wu,
        const float* __restrict__ ubias, const __half* __restrict__ gateh,
        const __half* __restrict__ rdh, __half* __restrict__ hr) {
    extern __shared__ __half sm[];
    __half* As = sm;
    __half* Bs = sm + STG2 * STAGE_H;

    const int tid = threadIdx.x, lane = tid & 31, wid = tid >> 5;
    const int wm = wid >> 2, wn = wid & 3;
    const int m0 = blockIdx.x * 128, n0 = blockIdx.y * 128;
    const int g  = blockIdx.y;
    const int kt = DIN >> 6;
    const int rw = tid >> 3, kc = tid & 7;

    float acc[4][4][4];
#pragma unroll
    for (int i = 0; i < 4; i++)
#pragma unroll
        for (int j = 0; j < 4; j++)
#pragma unroll
            for (int k = 0; k < 4; k++) acc[i][j][k] = 0.f;

    auto issue = [&](int t) {
        int slot = t % STG2;
        __half* as = As + slot * STAGE_H;
        __half* bs = Bs + slot * STAGE_H;
        int k0 = t << 6;
#pragma unroll
        for (int j = 0; j < 4; j++) {
            int row = rw + 32 * j;
            uint32_t so = (uint32_t)row * 64 + (uint32_t)((kc ^ (row & 7)) * 8);
            cpasync16(as + so, xru + (size_t)(m0 + row) * DIN + k0 + kc * 8);
            cpasync16(bs + so, Wu  + (size_t)(n0 + row) * DIN + k0 + kc * 8);
        }
    };

    issue(0);
    asm volatile("cp.async.commit_group;");
    issue(1);
    asm volatile("cp.async.commit_group;");

    for (int t = 0; t < kt; t++) {
        asm volatile("cp.async.wait_group %0;" :: "n"(1));
        __syncthreads();
        int nt = t + 2;
        if (nt < kt) issue(nt);
        asm volatile("cp.async.commit_group;");

        int slot = t % STG2;
        const __half* as = As + slot * STAGE_H;
        const __half* bs = Bs + slot * STAGE_H;
#pragma unroll
        for (int kk = 0; kk < 4; kk++) {
            uint32_t af[4][4], bf[4][2];
#pragma unroll
            for (int mi = 0; mi < 4; mi++) {
                int ar = wm * 64 + mi * 16 + (lane & 15);
                int ch = kk * 2 + (lane >> 4);
                const __half* p = as + ar * 64 + ((ch ^ (ar & 7)) * 8);
                ldm4(af[mi][0], af[mi][1], af[mi][2], af[mi][3], p);
            }
#pragma unroll
            for (int nb = 0; nb < 2; nb++) {
                int br = wn * 32 + nb * 16 + (lane & 7) + ((lane >> 4) << 3);
                int ch = kk * 2 + ((lane >> 3) & 1);
                const __half* p = bs + br * 64 + ((ch ^ (br & 7)) * 8);
                uint32_t q0, q1, q2, q3;
                ldm4(q0, q1, q2, q3, p);
                bf[nb * 2][0] = q0; bf[nb * 2][1] = q1;
                bf[nb * 2 + 1][0] = q2; bf[nb * 2 + 1][1] = q3;
            }
#pragma unroll
            for (int mi = 0; mi < 4; mi++)
#pragma unroll
                for (int ni = 0; ni < 4; ni++)
                    mma16816(acc[mi][ni], af[mi], bf[ni]);
        }
    }
    __syncthreads();   // mainloop smem reads complete before stage reuse

    // kick Rd[g] load into Bs slabs 0/1 (32 KB) — latency hidden by SwiGLU math
    {
        int row = tid >> 1, hf = tid & 1;
        const __half* src = rdh + (size_t)g * (128 * 128) + row * 128 + hf * 64;
        uint32_t base = (uint32_t)row * 64;
#pragma unroll
        for (int c = 0; c < 8; c++) {
            uint32_t so = (uint32_t)hf * STAGE_H + base + (uint32_t)((c ^ (row & 7)) * 8);
            cpasync16(Bs + so, src + c * 8);
        }
    }
    asm volatile("cp.async.commit_group;");

    // SwiGLU epilogue -> fp16 h tile into As slabs 0/1
    const int crow = wm * 64 + (lane >> 2);
    const int ccol = wn * 32 + (lane & 3) * 2;
#pragma unroll
    for (int mi = 0; mi < 4; mi++) {
#pragma unroll
        for (int ni = 0; ni < 4; ni++) {
            int r  = crow + mi * 16;
            int c  = ccol + ni * 8;
            int gr = m0 + r;
            int gc = n0 + c;
            float b0 = ubias[gc], b1 = ubias[gc + 1];
            float v0 = acc[mi][ni][0] + b0, v1 = acc[mi][ni][1] + b1;
            float v2 = acc[mi][ni][2] + b0, v3 = acc[mi][ni][3] + b1;
            __half2 ga = *reinterpret_cast<const __half2*>(&gateh[(size_t)gr * DINT + gc]);
            __half2 gb = *reinterpret_cast<const __half2*>(&gateh[(size_t)(gr + 8) * DINT + gc]);
            float g0 = __half2float(ga.x), g1 = __half2float(ga.y);
            float g2 = __half2float(gb.x), g3 = __half2float(gb.y);
            v0 *= g0 / (1.f + __expf(-g0));
            v1 *= g1 / (1.f + __expf(-g1));
            v2 *= g2 / (1.f + __expf(-g2));
            v3 *= g3 / (1.f + __expf(-g3));
            int slab = c >> 6, cc = c & 63, chunk = cc >> 3, win = cc & 7;
            uint32_t off = (uint32_t)slab * STAGE_H + ((uint32_t)(chunk ^ (r & 7)) * 8) + win;
            *reinterpret_cast<__half2*>(&As[off + (uint32_t)r * 64]) =
                __floats2half2_rn(v0, v1);
            *reinterpret_cast<__half2*>(&As[off + (uint32_t)(r + 8) * 64]) =
                __floats2half2_rn(v2, v3);
        }
    }
    asm volatile("cp.async.wait_group %0;" :: "n"(0));
    __syncthreads();

    // rotation GEMM: hr_tile = h_tile @ Rd[g]^T, K=128 (2 slabs x 4 kk)
#pragma unroll
    for (int i = 0; i < 4; i++)
#pragma unroll
        for (int j = 0; j < 4; j++)
#pragma unroll
            for (int k = 0; k < 4; k++) acc[i][j][k] = 0.f;

#pragma unroll
    for (int t2 = 0; t2 < 2; t2++) {
        const __half* as = As + t2 * STAGE_H;
        const __half* bs = Bs + t2 * STAGE_H;
#pragma unroll
        for (int kk = 0; kk < 4; kk++) {
            uint32_t af[4][4], bf[4][2];
#pragma unroll
            for (int mi = 0; mi < 4; mi++) {
                int ar = wm * 64 + mi * 16 + (lane & 15);
                int ch = kk * 2 + (lane >> 4);
                const __half* p = as + ar * 64 + ((ch ^ (ar & 7)) * 8);
                ldm4(af[mi][0], af[mi][1], af[mi][2], af[mi][3], p);
            }
#pragma unroll
            for (int nb = 0; nb < 2; nb++) {
                int br = wn * 32 + nb * 16 + (lane & 7) + ((lane >> 4) << 3);
                int ch = kk * 2 + ((lane >> 3) & 1);
                const __half* p = bs + br * 64 + ((ch ^ (br & 7)) * 8);
                uint32_t q0, q1, q2, q3;
                ldm4(q0, q1, q2, q3, p);
                bf[nb * 2][0] = q0; bf[nb * 2][1] = q1;
                bf[nb * 2 + 1][0] = q2; bf[nb * 2 + 1][1] = q3;
            }
#pragma unroll
            for (int mi = 0; mi < 4; mi++)
#pragma unroll
                for (int ni = 0; ni < 4; ni++)
                    mma16816(acc[mi][ni], af[mi], bf[ni]);
        }
    }

#pragma unroll
    for (int mi = 0; mi < 4; mi++) {
#pragma unroll
        for (int ni = 0; ni < 4; ni++) {
            int gr = m0 + crow + mi * 16;
            int gc = n0 + ccol + ni * 8;
            *reinterpret_cast<__half2*>(&hr[(size_t)gr * DINT + gc]) =
                __floats2half2_rn(acc[mi][ni][0], acc[mi][ni][1]);
            *reinterpret_cast<__half2*>(&hr[(size_t)(gr + 8) * DINT + gc]) =
                __floats2half2_rn(acc[mi][ni][2], acc[mi][ni][3]);
        }
    }
}

// ---------------- phase 1 (unchanged) ----------------
#define DQ_BPM   2048
#define DQ_INT4  ((long)DQ_BPM * 256)

__global__ void __launch_bounds__(256, 2)
k_phase1(const __half* __restrict__ xh,
         const __half* __restrict__ rgh, const __half* __restrict__ ruh,
         __half* __restrict__ xrg, __half* __restrict__ xru,
         const int* __restrict__ gp, const int* __restrict__ upk, const int* __restrict__ dpk,
         const float* __restrict__ cb,
         const float* __restrict__ gn, const float* __restrict__ un, const float* __restrict__ dn,
         __half* __restrict__ wg, __half* __restrict__ wu, __half* __restrict__ wd) {
    extern __shared__ __half sm[];
    const int tid = threadIdx.x;

    if (blockIdx.x >= 256) {
        float* lut = (float*)sm;
        if (tid < 16) lut[tid] = cb[tid] * 0.08838834764831845f;
        __syncthreads();
        int j = blockIdx.x - 256;
        int z = j / DQ_BPM, bb = j % DQ_BPM;
        const int* packed  = (z == 0) ? gp : (z == 1) ? upk : dpk;
        const float* norms = (z == 0) ? gn : (z == 1) ? un  : dn;
        __half* out        = (z == 0) ? wg : (z == 1) ? wu  : wd;
        const int K  = (z == 2) ? DINT : DIN;
        const int Kh = K >> 1;
        const int ng = K >> 7;
        long base = (long)bb * 256 + tid;
        int4 pk[4];
        float s[4];
        long idx[4];
#pragma unroll
        for (int p = 0; p < 4; p++) {
            idx[p] = base + p * DQ_INT4;
            pk[p] = reinterpret_cast<const int4*>(packed)[idx[p]];
            long p0 = idx[p] * 4;
            int n  = (int)(p0 / Kh);
            int k0 = (int)(p0 % Kh) * 2;
            s[p] = norms[(long)n * ng + (k0 >> 7)];
        }
#pragma unroll
        for (int p = 0; p < 4; p++) {
            uint4 o;
            o.x = pack2(pk[p].x, lut, s[p]);
            o.y = pack2(pk[p].y, lut, s[p]);
            o.z = pack2(pk[p].z, lut, s[p]);
            o.w = pack2(pk[p].w, lut, s[p]);
            reinterpret_cast<uint4*>(out)[idx[p]] = o;
        }
        return;
    }

    // rotation GEMM branch (K=128, BK=32, 4 ktiles)
    __half* As = sm;
    __half* Bs = sm + STAGES * 128 * SLDK;

    const int path = blockIdx.x >> 7;
    const int r    = blockIdx.x & 127;
    const int m0   = (r & 7) * 128;
    const int grp  = r >> 3;
    const __half* Ab = xh + grp * 128;
    const __half* Bb = (path ? ruh : rgh) + (size_t)grp * 128 * 128;
    __half* Ch = path ? xru : xrg;
    const int colBase = grp * 128;

    const int lane = tid & 31, wid = tid >> 5;
    const int wm = wid >> 2, wn = wid & 3;

    float acc[4][4][4];
#pragma unroll
    for (int i = 0; i < 4; i++)
#pragma unroll
        for (int jj = 0; jj < 4; jj++)
#pragma unroll
            for (int k = 0; k < 4; k++) acc[i][jj][k] = 0.f;

    const int c1 = tid, c2 = tid + 256;
    const int r1 = c1 >> 2, kc1 = c1 & 3, r2 = c2 >> 2, kc2 = c2 & 3;

    auto issue = [&](int t) {
        int slot = t & (STAGES - 1);
        __half* as = As + slot * 128 * SLDK;
        __half* bs = Bs + slot * 128 * SLDK;
        int k0 = t << 5;
        cpasync16(as + r1 * SLDK + kc1 * 8, Ab + (size_t)(m0 + r1) * DIN + k0 + kc1 * 8);
        cpasync16(as + r2 * SLDK + kc2 * 8, Ab + (size_t)(m0 + r2) * DIN + k0 + kc2 * 8);
        cpasync16(bs + r1 * SLDK + kc1 * 8, Bb + (size_t)r1 * 128 + k0 + kc1 * 8);
        cpasync16(bs + r2 * SLDK + kc2 * 8, Bb + (size_t)r2 * 128 + k0 + kc2 * 8);
    };

#pragma unroll
    for (int t = 0; t < STAGES - 1; t++) {
        issue(t);
        asm volatile("cp.async.commit_group;");
    }

#pragma unroll
    for (int t = 0; t < 4; t++) {
        asm volatile("cp.async.wait_group %0;" :: "n"(STAGES - 2));
        __syncthreads();
        if (t == 0) issue(3);
        asm volatile("cp.async.commit_group;");

        int slot = t & (STAGES - 1);
        const __half* as = As + slot * 128 * SLDK;
        const __half* bs = Bs + slot * 128 * SLDK;
#pragma unroll
        for (int kk = 0; kk < 2; kk++) {
            uint32_t af[4][4], bf[4][2];
#pragma unroll
            for (int mi = 0; mi < 4; mi++) {
                const __half* p = as + (wm * 64 + mi * 16 + (lane & 15)) * SLDK
                                     + kk * 16 + (lane >> 4) * 8;
                ldm4(af[mi][0], af[mi][1], af[mi][2], af[mi][3], p);
            }
#pragma unroll
            for (int nb = 0; nb < 2; nb++) {
                const __half* p = bs + (wn * 32 + nb * 16 + (lane & 7) + ((lane >> 4) << 3)) * SLDK
                                     + kk * 16 + (((lane >> 3) & 1) << 3);
                uint32_t q0, q1, q2, q3;
                ldm4(q0, q1, q2, q3, p);
                bf[nb * 2][0] = q0; bf[nb * 2][1] = q1;
                bf[nb * 2 + 1][0] = q2; bf[nb * 2 + 1][1] = q3;
            }
#pragma unroll
            for (int mi = 0; mi < 4; mi++)
#pragma unroll
                for (int ni = 0; ni < 4; ni++)
                    mma16816(acc[mi][ni], af[mi], bf[ni]);
        }
    }

    const int crow = wm * 64 + (lane >> 2);
    const int ccol = wn * 32 + (lane & 3) * 2;
#pragma unroll
    for (int mi = 0; mi < 4; mi++) {
#pragma unroll
        for (int ni = 0; ni < 4; ni++) {
            int gr = m0 + crow + mi * 16;
            int gc = colBase + ccol + ni * 8;
            *reinterpret_cast<__half2*>(&Ch[(size_t)gr * DIN + gc]) =
                __floats2half2_rn(acc[mi][ni][0], acc[mi][ni][1]);
            *reinterpret_cast<__half2*>(&Ch[(size_t)(gr + 8) * DIN + gc]) =
                __floats2half2_rn(acc[mi][ni][2], acc[mi][ni][3]);
        }
    }
}

// ---------------- host ----------------
template<typename T>
static void* symaddr(T& sym_) {
    void* p = nullptr;
    cudaGetSymbolAddress(&p, sym_);
    return p;
}

extern "C" void kernel_launch(void* const* d_in, const int* in_sizes, int n_in,
                              void* d_out, int out_size) {
    (void)in_sizes; (void)n_in; (void)out_size;
    const float* x     = (const float*)d_in[0];
    const float* cb    = (const float*)d_in[1];
    const float* gnorm = (const float*)d_in[2];
    const float* gbias = (const float*)d_in[3];
    const float* unorm = (const float*)d_in[4];
    const float* ubias = (const float*)d_in[5];
    const float* dnorm = (const float*)d_in[6];
    const float* dbias = (const float*)d_in[7];
    const float* rotg  = (const float*)d_in[8];
    const float* rotu  = (const float*)d_in[9];
    const float* rotd  = (const float*)d_in[10];
    const int*   gp    = (const int*)d_in[11];
    const int*   up_   = (const int*)d_in[12];
    const int*   dp    = (const int*)d_in[13];
    float* out = (float*)d_out;

    __half* xh    = (__half*)symaddr(g_x_h);
    __half* rgh   = (__half*)symaddr(g_rotg_h);
    __half* ruh   = (__half*)symaddr(g_rotu_h);
    __half* rdh   = (__half*)symaddr(g_rotd_h);
    __half* Wg    = (__half*)symaddr(g_Wg);
    __half* Wu    = (__half*)symaddr(g_Wu);
    __half* Wd    = (__half*)symaddr(g_Wd);
    __half* xrg   = (__half*)symaddr(g_xrg);
    __half* xru   = (__half*)symaddr(g_xru);
    __half* gateh = (__half*)symaddr(g_gate);
    __half* hr    = (__half*)symaddr(g_hr);
    float*  part  = (float*)symaddr(g_part);

    const int TPB = 256;
    const int smemP1 = STAGES * 2 * 128 * SLDK * (int)sizeof(__half); // 81920
    cudaFuncSetAttribute(k_gemm<2>, cudaFuncAttributeMaxDynamicSharedMemorySize, SMEM_G2);
    cudaFuncSetAttribute(k_gemm<4>, cudaFuncAttributeMaxDynamicSharedMemorySize, SMEM_G2);
    cudaFuncSetAttribute(k_uprot,   cudaFuncAttributeMaxDynamicSharedMemorySize, SMEM_G2);
    cudaFuncSetAttribute(k_phase1,  cudaFuncAttributeMaxDynamicSharedMemorySize, smemP1);

    // all fp32 -> fp16 converts in one launch
    k_convert_all<<<(CVT_TOT + TPB - 1) / TPB, TPB>>>(
        (const float4*)x, (const float4*)rotg, (const float4*)rotu, (const float4*)rotd,
        (__half2*)xh, (__half2*)rgh, (__half2*)ruh, (__half2*)rdh);

    // phase 1: both x-rotations + all three dequants
    k_phase1<<<256 + 3 * DQ_BPM, TPB, smemP1>>>(
        xh, rgh, ruh, xrg, xru, gp, up_, dp, cb, gnorm, unorm, dnorm, Wg, Wu, Wd);

    // gate = xrg @ Wg^T + gbias  (fp16 out)
    k_gemm<2><<<dim3(BB / 128, DINT / 128, 1), 256, SMEM_G2>>>(
        xrg, Wg, gbias, nullptr, gateh, BB, DINT, DIN, DIN, DIN, DINT, 0, 0, 0, 0);

    // fused: u-GEMM + SwiGLU + per-group h rotation -> hr directly
    k_uprot<<<dim3(BB / 128, DINT / 128), 256, SMEM_G2>>>(
        xru, Wu, ubias, gateh, rdh, hr);

    // down GEMM split-K=2
    k_gemm<4><<<dim3(BB / 128, DIN / 128, 2), 256, SMEM_G2>>>(
        hr, Wd, nullptr, nullptr, part, BB, DIN, DINT / 2, DINT, DINT, DIN,
        DINT / 2, DINT / 2, 0, BB * DIN);

    // out = part0 + part1 + dbias
    {
        int n4r = BB * DIN / 4;
        k_reduce2<<<(n4r + TPB - 1) / TPB, TPB>>>(
            (const float4*)part, (const float4*)(part + BB * DIN), dbias,
            (float4*)out, n4r, DIN / 4);
    }
}

// round 16
// speedup vs baseline: 1.0625x; 1.0398x over previous
#include <cuda_runtime.h>
#include <cuda_fp16.h>
#include <cstdint>
#include <math.h>

// ---------------- problem dims ----------------
#define BB    1024
#define DIN   2048
#define DINT  8192
#define NGIN  16
#define NGINT 64

// ---------------- scratch (device globals) ----------------
__device__ __half g_x_h  [BB * DIN];
__device__ __half g_rotg_h[NGIN  * 128 * 128];
__device__ __half g_rotu_h[NGIN  * 128 * 128];
__device__ __half g_rotd_h[NGINT * 128 * 128];
__device__ __half g_Wg   [DINT * DIN];
__device__ __half g_Wu   [DINT * DIN];
__device__ __half g_Wd   [DIN * DINT];
__device__ __half g_xrg  [BB * DIN];
__device__ __half g_xru  [BB * DIN];
__device__ __half g_gate [BB * DINT];
__device__ __half g_hr   [BB * DINT];
__device__ float  g_part [2 * BB * DIN];

// ---------------- converts (one launch) ----------------
#define CVT_N0 (BB * DIN / 4)
#define CVT_N1 (NGIN * 128 * 128 / 4)
#define CVT_N2 (NGIN * 128 * 128 / 4)
#define CVT_N3 (NGINT * 128 * 128 / 4)
#define CVT_TOT (CVT_N0 + CVT_N1 + CVT_N2 + CVT_N3)

__global__ void k_convert_all(const float4* __restrict__ x, const float4* __restrict__ rg,
                              const float4* __restrict__ ru, const float4* __restrict__ rd,
                              __half2* __restrict__ ox, __half2* __restrict__ org,
                              __half2* __restrict__ oru, __half2* __restrict__ ord) {
    int i = blockIdx.x * blockDim.x + threadIdx.x;
    if (i >= CVT_TOT) return;
    const float4* in;
    __half2* out;
    int j = i;
    if (j < CVT_N0)                       { in = x;  out = ox;  }
    else if ((j -= CVT_N0) < CVT_N1)      { in = rg; out = org; }
    else if ((j -= CVT_N1) < CVT_N2)      { in = ru; out = oru; }
    else { j -= CVT_N2;                     in = rd; out = ord; }
    float4 v = in[j];
    out[2 * j]     = __floats2half2_rn(v.x, v.y);
    out[2 * j + 1] = __floats2half2_rn(v.z, v.w);
}

__device__ __forceinline__ uint32_t pack2(int v, const float* lut, float s) {
    __half2 h = __floats2half2_rn(lut[v & 15] * s, lut[(v >> 4) & 15] * s);
    return *reinterpret_cast<uint32_t*>(&h);
}

__global__ void k_reduce2(const float4* __restrict__ p0, const float4* __restrict__ p1,
                          const float* __restrict__ bias, float4* __restrict__ out,
                          int n4, int ldc4) {
    int i = blockIdx.x * blockDim.x + threadIdx.x;
    if (i >= n4) return;
    float4 a = p0[i], b = p1[i];
    int c4 = i % ldc4;
    const float4 bv = reinterpret_cast<const float4*>(bias)[c4];
    float4 o;
    o.x = a.x + b.x + bv.x;
    o.y = a.y + b.y + bv.y;
    o.z = a.z + b.z + bv.z;
    o.w = a.w + b.w + bv.w;
    out[i] = o;
}

// ---------------- GEMM machinery ----------------
#define STAGES 4     // phase1 rot-GEMM (BK=32 legacy path)
#define SLDK   40
#define STG2   3
#define STAGE_H (128 * 64)
#define SMEM_G2 (STG2 * STAGE_H * 2 * 2)   // 98304 B

#define DQ_BPM   2048
#define DQ_INT4  ((long)DQ_BPM * 256)

__device__ __forceinline__ void cpasync16(void* s, const void* g) {
    uint32_t sa = (uint32_t)__cvta_generic_to_shared(s);
    asm volatile("cp.async.cg.shared.global [%0], [%1], 16;\n" :: "r"(sa), "l"(g));
}
__device__ __forceinline__ void ldm4(uint32_t& r0, uint32_t& r1, uint32_t& r2, uint32_t& r3,
                                     const void* p) {
    uint32_t a = (uint32_t)__cvta_generic_to_shared(p);
    asm volatile("ldmatrix.sync.aligned.m8n8.x4.shared.b16 {%0,%1,%2,%3}, [%4];"
                 : "=r"(r0), "=r"(r1), "=r"(r2), "=r"(r3) : "r"(a));
}
__device__ __forceinline__ void mma16816(float* c, const uint32_t* a, const uint32_t* b) {
    asm volatile(
        "mma.sync.aligned.m16n8k16.row.col.f32.f16.f16.f32 "
        "{%0,%1,%2,%3}, {%4,%5,%6,%7}, {%8,%9}, {%0,%1,%2,%3};"
        : "+f"(c[0]), "+f"(c[1]), "+f"(c[2]), "+f"(c[3])
        : "r"(a[0]), "r"(a[1]), "r"(a[2]), "r"(a[3]), "r"(b[0]), "r"(b[1]));
}

// dequant block body: 256 threads x 4 int4 chunks -> 8192 fp16 weights
__device__ __forceinline__ void dequant_block(const int* __restrict__ packed,
                                              const float* __restrict__ norms,
                                              __half* __restrict__ out,
                                              int K, int bb, int tid, const float* lut) {
    const int Kh = K >> 1;
    const int ng = K >> 7;
    long base = (long)bb * 256 + tid;
    int4 pk[4];
    float s[4];
    long idx[4];
#pragma unroll
    for (int p = 0; p < 4; p++) {
        idx[p] = base + p * DQ_INT4;
        pk[p] = reinterpret_cast<const int4*>(packed)[idx[p]];
        long p0 = idx[p] * 4;
        int n  = (int)(p0 / Kh);
        int k0 = (int)(p0 % Kh) * 2;
        s[p] = norms[(long)n * ng + (k0 >> 7)];
    }
#pragma unroll
    for (int p = 0; p < 4; p++) {
        uint4 o;
        o.x = pack2(pk[p].x, lut, s[p]);
        o.y = pack2(pk[p].y, lut, s[p]);
        o.z = pack2(pk[p].z, lut, s[p]);
        o.w = pack2(pk[p].w, lut, s[p]);
        reinterpret_cast<uint4*>(out)[idx[p]] = o;
    }
}

// EPI: 4 = raw float out (split-K partial).
template<int EPI>
__global__ void __launch_bounds__(256, 2)
k_gemm(const __half* __restrict__ A, const __half* __restrict__ B,
       const float* __restrict__ bias, const __half* __restrict__ aux,
       void* __restrict__ C,
       int M, int N, int K, int lda, int ldb, int ldc,
       int aColOff, int bBatch, int cColOff, int cBatch) {
    extern __shared__ __half sm[];
    __half* As = sm;
    __half* Bs = sm + STG2 * STAGE_H;

    const int tid = threadIdx.x, lane = tid & 31, wid = tid >> 5;
    const int wm = wid >> 2, wn = wid & 3;
    const int m0 = blockIdx.x * 128, n0 = blockIdx.y * 128;
    const __half* Ab = A + (size_t)blockIdx.z * aColOff;
    const __half* Bb = B + (size_t)blockIdx.z * bBatch;
    const int kt = K >> 6;

    float acc[4][4][4];
#pragma unroll
    for (int i = 0; i < 4; i++)
#pragma unroll
        for (int j = 0; j < 4; j++)
#pragma unroll
            for (int k = 0; k < 4; k++) acc[i][j][k] = 0.f;

    const int rw = tid >> 3;
    const int kc = tid & 7;

    auto issue = [&](int t) {
        int slot = t % STG2;
        __half* as = As + slot * STAGE_H;
        __half* bs = Bs + slot * STAGE_H;
        int k0 = t << 6;
#pragma unroll
        for (int j = 0; j < 4; j++) {
            int row = rw + 32 * j;
            uint32_t so = (uint32_t)row * 64 + (uint32_t)((kc ^ (row & 7)) * 8);
            cpasync16(as + so, Ab + (size_t)(m0 + row) * lda + k0 + kc * 8);
            cpasync16(bs + so, Bb + (size_t)(n0 + row) * ldb + k0 + kc * 8);
        }
    };

    issue(0);
    asm volatile("cp.async.commit_group;");
    if (1 < kt) issue(1);
    asm volatile("cp.async.commit_group;");

    for (int t = 0; t < kt; t++) {
        asm volatile("cp.async.wait_group %0;" :: "n"(1));
        __syncthreads();
        int nt = t + 2;
        if (nt < kt) issue(nt);
        asm volatile("cp.async.commit_group;");

        int slot = t % STG2;
        const __half* as = As + slot * STAGE_H;
        const __half* bs = Bs + slot * STAGE_H;
#pragma unroll
        for (int kk = 0; kk < 4; kk++) {
            uint32_t af[4][4], bf[4][2];
#pragma unroll
            for (int mi = 0; mi < 4; mi++) {
                int ar = wm * 64 + mi * 16 + (lane & 15);
                int ch = kk * 2 + (lane >> 4);
                const __half* p = as + ar * 64 + ((ch ^ (ar & 7)) * 8);
                ldm4(af[mi][0], af[mi][1], af[mi][2], af[mi][3], p);
            }
#pragma unroll
            for (int nb = 0; nb < 2; nb++) {
                int br = wn * 32 + nb * 16 + (lane & 7) + ((lane >> 4) << 3);
                int ch = kk * 2 + ((lane >> 3) & 1);
                const __half* p = bs + br * 64 + ((ch ^ (br & 7)) * 8);
                uint32_t q0, q1, q2, q3;
                ldm4(q0, q1, q2, q3, p);
                bf[nb * 2][0] = q0; bf[nb * 2][1] = q1;
                bf[nb * 2 + 1][0] = q2; bf[nb * 2 + 1][1] = q3;
            }
#pragma unroll
            for (int mi = 0; mi < 4; mi++)
#pragma unroll
                for (int ni = 0; ni < 4; ni++)
                    mma16816(acc[mi][ni], af[mi], bf[ni]);
        }
    }

    const int crow = wm * 64 + (lane >> 2);
    const int ccol = wn * 32 + (lane & 3) * 2;
#pragma unroll
    for (int mi = 0; mi < 4; mi++) {
#pragma unroll
        for (int ni = 0; ni < 4; ni++) {
            int gr = m0 + crow + mi * 16;
            int gc = n0 + ccol + ni * 8 + blockIdx.z * cColOff;
            float v0 = acc[mi][ni][0], v1 = acc[mi][ni][1];
            float v2 = acc[mi][ni][2], v3 = acc[mi][ni][3];
            if (EPI == 4) {
                float* Cf = (float*)C + (size_t)blockIdx.z * cBatch;
                *reinterpret_cast<float2*>(&Cf[(size_t)gr * ldc + gc])       = make_float2(v0, v1);
                *reinterpret_cast<float2*>(&Cf[(size_t)(gr + 8) * ldc + gc]) = make_float2(v2, v3);
            } else {
                __half* Ch = (__half*)C;
                *reinterpret_cast<__half2*>(&Ch[(size_t)gr * ldc + gc])       = __floats2half2_rn(v0, v1);
                *reinterpret_cast<__half2*>(&Ch[(size_t)(gr + 8) * ldc + gc]) = __floats2half2_rn(v2, v3);
            }
        }
    }
}

// ---------------- gate GEMM + Wu/Wd dequant in ONE launch ----------------
// blocks [0,512): gate tile, m0=(b&7)*128, n0=(b>>3)*128 (scheduled first).
// blocks [512, 512+2*2048): dequant; z = (b-512)/2048 (0 -> Wu, 1 -> Wd).
__global__ void __launch_bounds__(256, 2)
k_gate_mix(const __half* __restrict__ xrg, const __half* __restrict__ Wg,
           const float* __restrict__ gbias, __half* __restrict__ gateh,
           const int* __restrict__ upk, const int* __restrict__ dpk,
           const float* __restrict__ cb,
           const float* __restrict__ un, const float* __restrict__ dn,
           __half* __restrict__ wu, __half* __restrict__ wd) {
    extern __shared__ __half sm[];
    const int tid = threadIdx.x;

    if (blockIdx.x >= 512) {
        float* lut = (float*)sm;
        if (tid < 16) lut[tid] = cb[tid] * 0.08838834764831845f;
        __syncthreads();
        int j = blockIdx.x - 512;
        int z = j / DQ_BPM, bb = j % DQ_BPM;
        if (z == 0) dequant_block(upk, un, wu, DIN,  bb, tid, lut);
        else        dequant_block(dpk, dn, wd, DINT, bb, tid, lut);
        return;
    }

    // ---- gate GEMM tile ----
    __half* As = sm;
    __half* Bs = sm + STG2 * STAGE_H;

    const int lane = tid & 31, wid = tid >> 5;
    const int wm = wid >> 2, wn = wid & 3;
    const int m0 = (blockIdx.x & 7) * 128, n0 = (blockIdx.x >> 3) * 128;
    const int kt = DIN >> 6;
    const int rw = tid >> 3, kc = tid & 7;

    float acc[4][4][4];
#pragma unroll
    for (int i = 0; i < 4; i++)
#pragma unroll
        for (int j = 0; j < 4; j++)
#pragma unroll
            for (int k = 0; k < 4; k++) acc[i][j][k] = 0.f;

    auto issue = [&](int t) {
        int slot = t % STG2;
        __half* as = As + slot * STAGE_H;
        __half* bs = Bs + slot * STAGE_H;
        int k0 = t << 6;
#pragma unroll
        for (int j = 0; j < 4; j++) {
            int row = rw + 32 * j;
            uint32_t so = (uint32_t)row * 64 + (uint32_t)((kc ^ (row & 7)) * 8);
            cpasync16(as + so, xrg + (size_t)(m0 + row) * DIN + k0 + kc * 8);
            cpasync16(bs + so, Wg  + (size_t)(n0 + row) * DIN + k0 + kc * 8);
        }
    };

    issue(0);
    asm volatile("cp.async.commit_group;");
    issue(1);
    asm volatile("cp.async.commit_group;");

    for (int t = 0; t < kt; t++) {
        asm volatile("cp.async.wait_group %0;" :: "n"(1));
        __syncthreads();
        int nt = t + 2;
        if (nt < kt) issue(nt);
        asm volatile("cp.async.commit_group;");

        int slot = t % STG2;
        const __half* as = As + slot * STAGE_H;
        const __half* bs = Bs + slot * STAGE_H;
#pragma unroll
        for (int kk = 0; kk < 4; kk++) {
            uint32_t af[4][4], bf[4][2];
#pragma unroll
            for (int mi = 0; mi < 4; mi++) {
                int ar = wm * 64 + mi * 16 + (lane & 15);
                int ch = kk * 2 + (lane >> 4);
                const __half* p = as + ar * 64 + ((ch ^ (ar & 7)) * 8);
                ldm4(af[mi][0], af[mi][1], af[mi][2], af[mi][3], p);
            }
#pragma unroll
            for (int nb = 0; nb < 2; nb++) {
                int br = wn * 32 + nb * 16 + (lane & 7) + ((lane >> 4) << 3);
                int ch = kk * 2 + ((lane >> 3) & 1);
                const __half* p = bs + br * 64 + ((ch ^ (br & 7)) * 8);
                uint32_t q0, q1, q2, q3;
                ldm4(q0, q1, q2, q3, p);
                bf[nb * 2][0] = q0; bf[nb * 2][1] = q1;
                bf[nb * 2 + 1][0] = q2; bf[nb * 2 + 1][1] = q3;
            }
#pragma unroll
            for (int mi = 0; mi < 4; mi++)
#pragma unroll
                for (int ni = 0; ni < 4; ni++)
                    mma16816(acc[mi][ni], af[mi], bf[ni]);
        }
    }

    const int crow = wm * 64 + (lane >> 2);
    const int ccol = wn * 32 + (lane & 3) * 2;
#pragma unroll
    for (int mi = 0; mi < 4; mi++) {
#pragma unroll
        for (int ni = 0; ni < 4; ni++) {
            int gr = m0 + crow + mi * 16;
            int gc = n0 + ccol + ni * 8;
            float b0 = gbias[gc], b1 = gbias[gc + 1];
            float v0 = acc[mi][ni][0] + b0, v1 = acc[mi][ni][1] + b1;
            float v2 = acc[mi][ni][2] + b0, v3 = acc[mi][ni][3] + b1;
            *reinterpret_cast<__half2*>(&gateh[(size_t)gr * DINT + gc]) =
                __floats2half2_rn(v0, v1);
            *reinterpret_cast<__half2*>(&gateh[(size_t)(gr + 8) * DINT + gc]) =
                __floats2half2_rn(v2, v3);
        }
    }
}

// ---------------- fused up + SwiGLU + h-rotation (unchanged from R15) ----------------
__global__ void __launch_bounds__(256, 2)
k_uprot(const __half* __restrict__ xru, const __half* __restrict__ Wu,
        const float* __restrict__ ubias, const __half* __restrict__ gateh,
        const __half* __restrict__ rdh, __half* __restrict__ hr) {
    extern __shared__ __half sm[];
    __half* As = sm;
    __half* Bs = sm + STG2 * STAGE_H;

    const int tid = threadIdx.x, lane = tid & 31, wid = tid >> 5;
    const int wm = wid >> 2, wn = wid & 3;
    const int m0 = blockIdx.x * 128, n0 = blockIdx.y * 128;
    const int g  = blockIdx.y;
    const int kt = DIN >> 6;
    const int rw = tid >> 3, kc = tid & 7;

    float acc[4][4][4];
#pragma unroll
    for (int i = 0; i < 4; i++)
#pragma unroll
        for (int j = 0; j < 4; j++)
#pragma unroll
            for (int k = 0; k < 4; k++) acc[i][j][k] = 0.f;

    auto issue = [&](int t) {
        int slot = t % STG2;
        __half* as = As + slot * STAGE_H;
        __half* bs = Bs + slot * STAGE_H;
        int k0 = t << 6;
#pragma unroll
        for (int j = 0; j < 4; j++) {
            int row = rw + 32 * j;
            uint32_t so = (uint32_t)row * 64 + (uint32_t)((kc ^ (row & 7)) * 8);
            cpasync16(as + so, xru + (size_t)(m0 + row) * DIN + k0 + kc * 8);
            cpasync16(bs + so, Wu  + (size_t)(n0 + row) * DIN + k0 + kc * 8);
        }
    };

    issue(0);
    asm volatile("cp.async.commit_group;");
    issue(1);
    asm volatile("cp.async.commit_group;");

    for (int t = 0; t < kt; t++) {
        asm volatile("cp.async.wait_group %0;" :: "n"(1));
        __syncthreads();
        int nt = t + 2;
        if (nt < kt) issue(nt);
        asm volatile("cp.async.commit_group;");

        int slot = t % STG2;
        const __half* as = As + slot * STAGE_H;
        const __half* bs = Bs + slot * STAGE_H;
#pragma unroll
        for (int kk = 0; kk < 4; kk++) {
            uint32_t af[4][4], bf[4][2];
#pragma unroll
            for (int mi = 0; mi < 4; mi++) {
                int ar = wm * 64 + mi * 16 + (lane & 15);
                int ch = kk * 2 + (lane >> 4);
                const __half* p = as + ar * 64 + ((ch ^ (ar & 7)) * 8);
                ldm4(af[mi][0], af[mi][1], af[mi][2], af[mi][3], p);
            }
#pragma unroll
            for (int nb = 0; nb < 2; nb++) {
                int br = wn * 32 + nb * 16 + (lane & 7) + ((lane >> 4) << 3);
                int ch = kk * 2 + ((lane >> 3) & 1);
                const __half* p = bs + br * 64 + ((ch ^ (br & 7)) * 8);
                uint32_t q0, q1, q2, q3;
                ldm4(q0, q1, q2, q3, p);
                bf[nb * 2][0] = q0; bf[nb * 2][1] = q1;
                bf[nb * 2 + 1][0] = q2; bf[nb * 2 + 1][1] = q3;
            }
#pragma unroll
            for (int mi = 0; mi < 4; mi++)
#pragma unroll
                for (int ni = 0; ni < 4; ni++)
                    mma16816(acc[mi][ni], af[mi], bf[ni]);
        }
    }
    __syncthreads();

    {
        int row = tid >> 1, hf = tid & 1;
        const __half* src = rdh + (size_t)g * (128 * 128) + row * 128 + hf * 64;
        uint32_t base = (uint32_t)row * 64;
#pragma unroll
        for (int c = 0; c < 8; c++) {
            uint32_t so = (uint32_t)hf * STAGE_H + base + (uint32_t)((c ^ (row & 7)) * 8);
            cpasync16(Bs + so, src + c * 8);
        }
    }
    asm volatile("cp.async.commit_group;");

    const int crow = wm * 64 + (lane >> 2);
    const int ccol = wn * 32 + (lane & 3) * 2;
#pragma unroll
    for (int mi = 0; mi < 4; mi++) {
#pragma unroll
        for (int ni = 0; ni < 4; ni++) {
            int r  = crow + mi * 16;
            int c  = ccol + ni * 8;
            int gr = m0 + r;
            int gc = n0 + c;
            float b0 = ubias[gc], b1 = ubias[gc + 1];
            float v0 = acc[mi][ni][0] + b0, v1 = acc[mi][ni][1] + b1;
            float v2 = acc[mi][ni][2] + b0, v3 = acc[mi][ni][3] + b1;
            __half2 ga = *reinterpret_cast<const __half2*>(&gateh[(size_t)gr * DINT + gc]);
            __half2 gb = *reinterpret_cast<const __half2*>(&gateh[(size_t)(gr + 8) * DINT + gc]);
            float g0 = __half2float(ga.x), g1 = __half2float(ga.y);
            float g2 = __half2float(gb.x), g3 = __half2float(gb.y);
            v0 *= g0 / (1.f + __expf(-g0));
            v1 *= g1 / (1.f + __expf(-g1));
            v2 *= g2 / (1.f + __expf(-g2));
            v3 *= g3 / (1.f + __expf(-g3));
            int slab = c >> 6, cc = c & 63, chunk = cc >> 3, win = cc & 7;
            uint32_t off = (uint32_t)slab * STAGE_H + ((uint32_t)(chunk ^ (r & 7)) * 8) + win;
            *reinterpret_cast<__half2*>(&As[off + (uint32_t)r * 64]) =
                __floats2half2_rn(v0, v1);
            *reinterpret_cast<__half2*>(&As[off + (uint32_t)(r + 8) * 64]) =
                __floats2half2_rn(v2, v3);
        }
    }
    asm volatile("cp.async.wait_group %0;" :: "n"(0));
    __syncthreads();

#pragma unroll
    for (int i = 0; i < 4; i++)
#pragma unroll
        for (int j = 0; j < 4; j++)
#pragma unroll
            for (int k = 0; k < 4; k++) acc[i][j][k] = 0.f;

#pragma unroll
    for (int t2 = 0; t2 < 2; t2++) {
        const __half* as = As + t2 * STAGE_H;
        const __half* bs = Bs + t2 * STAGE_H;
#pragma unroll
        for (int kk = 0; kk < 4; kk++) {
            uint32_t af[4][4], bf[4][2];
#pragma unroll
            for (int mi = 0; mi < 4; mi++) {
                int ar = wm * 64 + mi * 16 + (lane & 15);
                int ch = kk * 2 + (lane >> 4);
                const __half* p = as + ar * 64 + ((ch ^ (ar & 7)) * 8);
                ldm4(af[mi][0], af[mi][1], af[mi][2], af[mi][3], p);
            }
#pragma unroll
            for (int nb = 0; nb < 2; nb++) {
                int br = wn * 32 + nb * 16 + (lane & 7) + ((lane >> 4) << 3);
                int ch = kk * 2 + ((lane >> 3) & 1);
                const __half* p = bs + br * 64 + ((ch ^ (br & 7)) * 8);
                uint32_t q0, q1, q2, q3;
                ldm4(q0, q1, q2, q3, p);
                bf[nb * 2][0] = q0; bf[nb * 2][1] = q1;
                bf[nb * 2 + 1][0] = q2; bf[nb * 2 + 1][1] = q3;
            }
#pragma unroll
            for (int mi = 0; mi < 4; mi++)
#pragma unroll
                for (int ni = 0; ni < 4; ni++)
                    mma16816(acc[mi][ni], af[mi], bf[ni]);
        }
    }

#pragma unroll
    for (int mi = 0; mi < 4; mi++) {
#pragma unroll
        for (int ni = 0; ni < 4; ni++) {
            int gr = m0 + crow + mi * 16;
            int gc = n0 + ccol + ni * 8;
            *reinterpret_cast<__half2*>(&hr[(size_t)gr * DINT + gc]) =
                __floats2half2_rn(acc[mi][ni][0], acc[mi][ni][1]);
            *reinterpret_cast<__half2*>(&hr[(size_t)(gr + 8) * DINT + gc]) =
                __floats2half2_rn(acc[mi][ni][2], acc[mi][ni][3]);
        }
    }
}

// ---------------- phase 1: x-rotations + Wg dequant only ----------------
__global__ void __launch_bounds__(256, 2)
k_phase1(const __half* __restrict__ xh,
         const __half* __restrict__ rgh, const __half* __restrict__ ruh,
         __half* __restrict__ xrg, __half* __restrict__ xru,
         const int* __restrict__ gp, const float* __restrict__ cb,
         const float* __restrict__ gn, __half* __restrict__ wg) {
    extern __shared__ __half sm[];
    const int tid = threadIdx.x;

    if (blockIdx.x >= 256) {
        float* lut = (float*)sm;
        if (tid < 16) lut[tid] = cb[tid] * 0.08838834764831845f;
        __syncthreads();
        dequant_block(gp, gn, wg, DIN, blockIdx.x - 256, tid, lut);
        return;
    }

    // rotation GEMM branch (K=128, BK=32, 4 ktiles)
    __half* As = sm;
    __half* Bs = sm + STAGES * 128 * SLDK;

    const int path = blockIdx.x >> 7;
    const int r    = blockIdx.x & 127;
    const int m0   = (r & 7) * 128;
    const int grp  = r >> 3;
    const __half* Ab = xh + grp * 128;
    const __half* Bb = (path ? ruh : rgh) + (size_t)grp * 128 * 128;
    __half* Ch = path ? xru : xrg;
    const int colBase = grp * 128;

    const int lane = tid & 31, wid = tid >> 5;
    const int wm = wid >> 2, wn = wid & 3;

    float acc[4][4][4];
#pragma unroll
    for (int i = 0; i < 4; i++)
#pragma unroll
        for (int jj = 0; jj < 4; jj++)
#pragma unroll
            for (int k = 0; k < 4; k++) acc[i][jj][k] = 0.f;

    const int c1 = tid, c2 = tid + 256;
    const int r1 = c1 >> 2, kc1 = c1 & 3, r2 = c2 >> 2, kc2 = c2 & 3;

    auto issue = [&](int t) {
        int slot = t & (STAGES - 1);
        __half* as = As + slot * 128 * SLDK;
        __half* bs = Bs + slot * 128 * SLDK;
        int k0 = t << 5;
        cpasync16(as + r1 * SLDK + kc1 * 8, Ab + (size_t)(m0 + r1) * DIN + k0 + kc1 * 8);
        cpasync16(as + r2 * SLDK + kc2 * 8, Ab + (size_t)(m0 + r2) * DIN + k0 + kc2 * 8);
        cpasync16(bs + r1 * SLDK + kc1 * 8, Bb + (size_t)r1 * 128 + k0 + kc1 * 8);
        cpasync16(bs + r2 * SLDK + kc2 * 8, Bb + (size_t)r2 * 128 + k0 + kc2 * 8);
    };

#pragma unroll
    for (int t = 0; t < STAGES - 1; t++) {
        issue(t);
        asm volatile("cp.async.commit_group;");
    }

#pragma unroll
    for (int t = 0; t < 4; t++) {
        asm volatile("cp.async.wait_group %0;" :: "n"(STAGES - 2));
        __syncthreads();
        if (t == 0) issue(3);
        asm volatile("cp.async.commit_group;");

        int slot = t & (STAGES - 1);
        const __half* as = As + slot * 128 * SLDK;
        const __half* bs = Bs + slot * 128 * SLDK;
#pragma unroll
        for (int kk = 0; kk < 2; kk++) {
            uint32_t af[4][4], bf[4][2];
#pragma unroll
            for (int mi = 0; mi < 4; mi++) {
                const __half* p = as + (wm * 64 + mi * 16 + (lane & 15)) * SLDK
                                     + kk * 16 + (lane >> 4) * 8;
                ldm4(af[mi][0], af[mi][1], af[mi][2], af[mi][3], p);
            }
#pragma unroll
            for (int nb = 0; nb < 2; nb++) {
                const __half* p = bs + (wn * 32 + nb * 16 + (lane & 7) + ((lane >> 4) << 3)) * SLDK
                                     + kk * 16 + (((lane >> 3) & 1) << 3);
                uint32_t q0, q1, q2, q3;
                ldm4(q0, q1, q2, q3, p);
                bf[nb * 2][0] = q0; bf[nb * 2][1] = q1;
                bf[nb * 2 + 1][0] = q2; bf[nb * 2 + 1][1] = q3;
            }
#pragma unroll
            for (int mi = 0; mi < 4; mi++)
#pragma unroll
                for (int ni = 0; ni < 4; ni++)
                    mma16816(acc[mi][ni], af[mi], bf[ni]);
        }
    }

    const int crow = wm * 64 + (lane >> 2);
    const int ccol = wn * 32 + (lane & 3) * 2;
#pragma unroll
    for (int mi = 0; mi < 4; mi++) {
#pragma unroll
        for (int ni = 0; ni < 4; ni++) {
            int gr = m0 + crow + mi * 16;
            int gc = colBase + ccol + ni * 8;
            *reinterpret_cast<__half2*>(&Ch[(size_t)gr * DIN + gc]) =
                __floats2half2_rn(acc[mi][ni][0], acc[mi][ni][1]);
            *reinterpret_cast<__half2*>(&Ch[(size_t)(gr + 8) * DIN + gc]) =
                __floats2half2_rn(acc[mi][ni][2], acc[mi][ni][3]);
        }
    }
}

// ---------------- host ----------------
template<typename T>
static void* symaddr(T& sym_) {
    void* p = nullptr;
    cudaGetSymbolAddress(&p, sym_);
    return p;
}

extern "C" void kernel_launch(void* const* d_in, const int* in_sizes, int n_in,
                              void* d_out, int out_size) {
    (void)in_sizes; (void)n_in; (void)out_size;
    const float* x     = (const float*)d_in[0];
    const float* cb    = (const float*)d_in[1];
    const float* gnorm = (const float*)d_in[2];
    const float* gbias = (const float*)d_in[3];
    const float* unorm = (const float*)d_in[4];
    const float* ubias = (const float*)d_in[5];
    const float* dnorm = (const float*)d_in[6];
    const float* dbias = (const float*)d_in[7];
    const float* rotg  = (const float*)d_in[8];
    const float* rotu  = (const float*)d_in[9];
    const float* rotd  = (const float*)d_in[10];
    const int*   gp    = (const int*)d_in[11];
    const int*   up_   = (const int*)d_in[12];
    const int*   dp    = (const int*)d_in[13];
    float* out = (float*)d_out;

    __half* xh    = (__half*)symaddr(g_x_h);
    __half* rgh   = (__half*)symaddr(g_rotg_h);
    __half* ruh   = (__half*)symaddr(g_rotu_h);
    __half* rdh   = (__half*)symaddr(g_rotd_h);
    __half* Wg    = (__half*)symaddr(g_Wg);
    __half* Wu    = (__half*)symaddr(g_Wu);
    __half* Wd    = (__half*)symaddr(g_Wd);
    __half* xrg   = (__half*)symaddr(g_xrg);
    __half* xru   = (__half*)symaddr(g_xru);
    __half* gateh = (__half*)symaddr(g_gate);
    __half* hr    = (__half*)symaddr(g_hr);
    float*  part  = (float*)symaddr(g_part);

    const int TPB = 256;
    const int smemP1 = STAGES * 2 * 128 * SLDK * (int)sizeof(__half); // 81920
    cudaFuncSetAttribute(k_gemm<4>,  cudaFuncAttributeMaxDynamicSharedMemorySize, SMEM_G2);
    cudaFuncSetAttribute(k_gate_mix, cudaFuncAttributeMaxDynamicSharedMemorySize, SMEM_G2);
    cudaFuncSetAttribute(k_uprot,    cudaFuncAttributeMaxDynamicSharedMemorySize, SMEM_G2);
    cudaFuncSetAttribute(k_phase1,   cudaFuncAttributeMaxDynamicSharedMemorySize, smemP1);

    // all fp32 -> fp16 converts in one launch
    k_convert_all<<<(CVT_TOT + TPB - 1) / TPB, TPB>>>(
        (const float4*)x, (const float4*)rotg, (const float4*)rotu, (const float4*)rotd,
        (__half2*)xh, (__half2*)rgh, (__half2*)ruh, (__half2*)rdh);

    // phase 1: both x-rotations + Wg dequant only
    k_phase1<<<256 + DQ_BPM, TPB, smemP1>>>(
        xh, rgh, ruh, xrg, xru, gp, cb, gnorm, Wg);

    // gate GEMM + Wu/Wd dequant hidden behind it (one heterogeneous launch)
    k_gate_mix<<<512 + 2 * DQ_BPM, TPB, SMEM_G2>>>(
        xrg, Wg, gbias, gateh, up_, dp, cb, unorm, dnorm, Wu, Wd);

    // fused: u-GEMM + SwiGLU + per-group h rotation -> hr directly
    k_uprot<<<dim3(BB / 128, DINT / 128), 256, SMEM_G2>>>(
        xru, Wu, ubias, gateh, rdh, hr);

    // down GEMM split-K=2
    k_gemm<4><<<dim3(BB / 128, DIN / 128, 2), 256, SMEM_G2>>>(
        hr, Wd, nullptr, nullptr, part, BB, DIN, DINT / 2, DINT, DINT, DIN,
        DINT / 2, DINT / 2, 0, BB * DIN);

    // out = part0 + part1 + dbias
    {
        int n4r = BB * DIN / 4;
        k_reduce2<<<(n4r + TPB - 1) / TPB, TPB>>>(
            (const float4*)part, (const float4*)(part + BB * DIN), dbias,
            (float4*)out, n4r, DIN / 4);
    }
}